// round 2
// baseline (speedup 1.0000x reference)
#include <cuda_runtime.h>
#include <cuda_bf16.h>

// Problem constants
#define Bx 4
#define Cx 3
#define Hx 224
#define Wx 224
#define Kx 196
#define Ex 768
#define HW (Hx * Wx)               // 50176
#define KC (Kx * Cx)               // 588

// Accumulate config: 49 blocks per batch, 256 threads, 4 pixels/thread (float4)
#define BPB 49
#define TA 256
#define PIX_PER_BLOCK (TA * 4)     // 1024; 49*1024 = 50176 = HW exactly

// Per-block partial sums; every slot written every call -> no zeroing kernel.
__device__ float g_partial[Bx * BPB * KC];   // 115248 floats = 461 KB

__global__ void accumulate_kernel(const float* __restrict__ img,
                                  const int* __restrict__ seg) {
    __shared__ float s_pool[KC];   // 588 floats

    const int b   = blockIdx.x / BPB;
    const int blk = blockIdx.x % BPB;

    for (int i = threadIdx.x; i < KC; i += TA) s_pool[i] = 0.0f;
    __syncthreads();

    const int p0 = blk * PIX_PER_BLOCK + threadIdx.x * 4;

    const float* img_b = img + (size_t)b * Cx * HW;
    const int*   seg_b = seg + (size_t)b * HW;

    // Vectorized loads: 1 int4 + 3 float4 per thread
    int4   s  = *(const int4*)  (seg_b + p0);
    float4 v0 = *(const float4*)(img_b + p0);
    float4 v1 = *(const float4*)(img_b + p0 + HW);
    float4 v2 = *(const float4*)(img_b + p0 + 2 * HW);

    atomicAdd(&s_pool[s.x * Cx + 0], v0.x);
    atomicAdd(&s_pool[s.x * Cx + 1], v1.x);
    atomicAdd(&s_pool[s.x * Cx + 2], v2.x);
    atomicAdd(&s_pool[s.y * Cx + 0], v0.y);
    atomicAdd(&s_pool[s.y * Cx + 1], v1.y);
    atomicAdd(&s_pool[s.y * Cx + 2], v2.y);
    atomicAdd(&s_pool[s.z * Cx + 0], v0.z);
    atomicAdd(&s_pool[s.z * Cx + 1], v1.z);
    atomicAdd(&s_pool[s.z * Cx + 2], v2.z);
    atomicAdd(&s_pool[s.w * Cx + 0], v0.w);
    atomicAdd(&s_pool[s.w * Cx + 1], v1.w);
    atomicAdd(&s_pool[s.w * Cx + 2], v2.w);

    __syncthreads();

    // Plain stores of this block's partials (private slot, no atomics)
    float* gp = g_partial + (size_t)blockIdx.x * KC;
    for (int i = threadIdx.x; i < KC; i += TA) gp[i] = s_pool[i];
}

// One block per (b,k): reduce 49 partials per channel, then 768 outputs.
__global__ void gemm_kernel(const float* __restrict__ Wmat,
                            const float* __restrict__ bias,
                            float* __restrict__ out) {
    const int bk = blockIdx.x;           // 0 .. B*K-1
    const int b  = bk / Kx;
    const int k  = bk % Kx;
    const int tid = threadIdx.x;

    __shared__ float sp[Cx];
    if (tid < Cx) sp[tid] = 0.0f;
    __syncthreads();

    // 49 blocks * 3 channels = 147 partials to reduce (L2-resident)
    if (tid < BPB * Cx) {
        int blk = tid / Cx;
        int c   = tid % Cx;
        float v = g_partial[((size_t)b * BPB + blk) * KC + k * Cx + c];
        atomicAdd(&sp[c], v);
    }
    __syncthreads();

    const float inv = 1.0f / (float)HW;
    float p0 = sp[0] * inv;
    float p1 = sp[1] * inv;
    float p2 = sp[2] * inv;

    const int e = tid;                    // 0 .. 767
    float acc = bias[e];
    acc = fmaf(p0, Wmat[0 * Ex + e], acc);
    acc = fmaf(p1, Wmat[1 * Ex + e], acc);
    acc = fmaf(p2, Wmat[2 * Ex + e], acc);

    out[(size_t)bk * Ex + e] = acc;
}

extern "C" void kernel_launch(void* const* d_in, const int* in_sizes, int n_in,
                              void* d_out, int out_size) {
    const float* img  = (const float*)d_in[0];
    const int*   seg  = (const int*)d_in[1];
    const float* Wmat = (const float*)d_in[2];
    const float* bias = (const float*)d_in[3];
    float* out = (float*)d_out;

    accumulate_kernel<<<Bx * BPB, TA>>>(img, seg);
    gemm_kernel<<<Bx * Kx, Ex>>>(Wmat, bias, out);
}

// round 3
// speedup vs baseline: 1.5791x; 1.5791x over previous
#include <cuda_runtime.h>
#include <cuda_bf16.h>

// Problem constants
#define Bx 4
#define Cx 3
#define Hx 224
#define Wx 224
#define Kx 196
#define Ex 768
#define HW (Hx * Wx)               // 50176
#define KC (Kx * Cx)               // 588
#define BK (Bx * Kx)               // 784

// Accumulate config: 49 blocks per batch, 256 threads, 4 pixels/thread (float4)
#define BPB 49
#define TA 256
#define PIX_PER_BLOCK (TA * 4)     // 1024; 49*1024 = 50176 = HW exactly

// Pooled sums. __device__ globals are zero-initialized at module load; the
// gemm kernel re-zeroes every row it consumes, so this is 0 at the start of
// every kernel_launch call (deterministic invariant, no zeroing launch).
__device__ float g_pooled[Bx * KC];

__global__ void accumulate_kernel(const float* __restrict__ img,
                                  const int* __restrict__ seg) {
    __shared__ float s_pool[KC];   // 588 floats

    const int b   = blockIdx.x / BPB;
    const int blk = blockIdx.x % BPB;

    for (int i = threadIdx.x; i < KC; i += TA) s_pool[i] = 0.0f;
    __syncthreads();

    const int p0 = blk * PIX_PER_BLOCK + threadIdx.x * 4;

    const float* img_b = img + (size_t)b * Cx * HW;
    const int*   seg_b = seg + (size_t)b * HW;

    int4   s  = *(const int4*)  (seg_b + p0);
    float4 v0 = *(const float4*)(img_b + p0);
    float4 v1 = *(const float4*)(img_b + p0 + HW);
    float4 v2 = *(const float4*)(img_b + p0 + 2 * HW);

    atomicAdd(&s_pool[s.x * Cx + 0], v0.x);
    atomicAdd(&s_pool[s.x * Cx + 1], v1.x);
    atomicAdd(&s_pool[s.x * Cx + 2], v2.x);
    atomicAdd(&s_pool[s.y * Cx + 0], v0.y);
    atomicAdd(&s_pool[s.y * Cx + 1], v1.y);
    atomicAdd(&s_pool[s.y * Cx + 2], v2.y);
    atomicAdd(&s_pool[s.z * Cx + 0], v0.z);
    atomicAdd(&s_pool[s.z * Cx + 1], v1.z);
    atomicAdd(&s_pool[s.z * Cx + 2], v2.z);
    atomicAdd(&s_pool[s.w * Cx + 0], v0.w);
    atomicAdd(&s_pool[s.w * Cx + 1], v1.w);
    atomicAdd(&s_pool[s.w * Cx + 2], v2.w);

    __syncthreads();

    // Flush block partials into the global pool
    float* gp = g_pooled + b * KC;
    for (int i = threadIdx.x; i < KC; i += TA) {
        atomicAdd(&gp[i], s_pool[i]);
    }
}

// 112 blocks x 768 threads; each block computes 7 (b,k) rows, reusing the
// W/bias registers, then zeroes the pooled rows it consumed.
#define ROWS_PER_BLOCK 7
#define GEMM_BLOCKS (BK / ROWS_PER_BLOCK)   // 112

__global__ void gemm_kernel(const float* __restrict__ Wmat,
                            const float* __restrict__ bias,
                            float* __restrict__ out) {
    const int e = threadIdx.x;              // 0 .. 767

    const float w0 = Wmat[0 * Ex + e];
    const float w1 = Wmat[1 * Ex + e];
    const float w2 = Wmat[2 * Ex + e];
    const float bb = bias[e];
    const float inv = 1.0f / (float)HW;

    const int bk0 = blockIdx.x * ROWS_PER_BLOCK;

#pragma unroll
    for (int r = 0; r < ROWS_PER_BLOCK; r++) {
        const int bk = bk0 + r;
        float p0 = g_pooled[bk * Cx + 0] * inv;   // broadcast loads
        float p1 = g_pooled[bk * Cx + 1] * inv;
        float p2 = g_pooled[bk * Cx + 2] * inv;

        float acc = bb;
        acc = fmaf(p0, w0, acc);
        acc = fmaf(p1, w1, acc);
        acc = fmaf(p2, w2, acc);
        out[(size_t)bk * Ex + e] = acc;
    }

    // All reads of this block's pooled rows are done; restore the
    // zero-invariant for the next kernel_launch call.
    __syncthreads();
    if (e < ROWS_PER_BLOCK * Cx) {
        g_pooled[bk0 * Cx + e] = 0.0f;
    }
}

extern "C" void kernel_launch(void* const* d_in, const int* in_sizes, int n_in,
                              void* d_out, int out_size) {
    const float* img  = (const float*)d_in[0];
    const int*   seg  = (const int*)d_in[1];
    const float* Wmat = (const float*)d_in[2];
    const float* bias = (const float*)d_in[3];
    float* out = (float*)d_out;

    accumulate_kernel<<<Bx * BPB, TA>>>(img, seg);
    gemm_kernel<<<GEMM_BLOCKS, Ex>>>(Wmat, bias, out);
}